// round 5
// baseline (speedup 1.0000x reference)
#include <cuda_runtime.h>

#define D_MODEL   1024
#define NUM_HEADS 16
#define HEAD_DIM  64
#define BATCH     2
#define SEQ       2048
#define MTOT      (BATCH * SEQ)   /* 4096 rows */

// ---------------------------------------------------------------------------
// Scratch (device globals; no allocation allowed)
// ---------------------------------------------------------------------------
__device__ float g_q[MTOT * D_MODEL];
__device__ float g_k[MTOT * D_MODEL];
__device__ float g_v[MTOT * D_MODEL];
__device__ float g_o[MTOT * D_MODEL];

// ---------------------------------------------------------------------------
// GEMM:  C[M,N] = A[M,K] @ B[N,K]^T   (row-major, K contiguous on both sides)
// 64x64 block tile, BK=16, 256 threads, 4x4 register micro-tile.
// ---------------------------------------------------------------------------
#define BM 64
#define BN 64
#define BK 16

__global__ __launch_bounds__(256) void gemm_nt_kernel(
    const float* __restrict__ A, const float* __restrict__ B,
    float* __restrict__ C, int M, int N, int K)
{
    __shared__ float As[BK][BM + 1];
    __shared__ float Bs[BK][BN + 1];

    const int tid = threadIdx.x;
    const int tx  = tid & 15;
    const int ty  = tid >> 4;
    const int m0  = blockIdx.y * BM;
    const int n0  = blockIdx.x * BN;

    float acc[4][4] = {};

    for (int k0 = 0; k0 < K; k0 += BK) {
        // Load 64x16 tiles of A and B (transposed into k-major smem)
        #pragma unroll
        for (int i = 0; i < 4; i++) {
            int e = tid + i * 256;     // 0..1023
            int r = e >> 4;            // 0..63
            int c = e & 15;            // 0..15
            As[c][r] = A[(size_t)(m0 + r) * K + k0 + c];
            Bs[c][r] = B[(size_t)(n0 + r) * K + k0 + c];
        }
        __syncthreads();

        #pragma unroll
        for (int kk = 0; kk < BK; kk++) {
            float a[4], b[4];
            #pragma unroll
            for (int i = 0; i < 4; i++) a[i] = As[kk][ty * 4 + i];
            #pragma unroll
            for (int j = 0; j < 4; j++) b[j] = Bs[kk][tx * 4 + j];
            #pragma unroll
            for (int i = 0; i < 4; i++)
                #pragma unroll
                for (int j = 0; j < 4; j++)
                    acc[i][j] += a[i] * b[j];
        }
        __syncthreads();
    }

    #pragma unroll
    for (int i = 0; i < 4; i++)
        #pragma unroll
        for (int j = 0; j < 4; j++)
            C[(size_t)(m0 + ty * 4 + i) * N + n0 + tx * 4 + j] = acc[i][j];
}

// ---------------------------------------------------------------------------
// Flash-attention style causal attention, fp32, online softmax.
// One block per (q-tile of 64 rows, head, batch). 256 threads.
// Q/K/V viewed as [B, T, D_MODEL] with head h occupying cols [h*64, h*64+64).
// ---------------------------------------------------------------------------
#define QT  64
#define KT  64
#define LDP 65   /* padded stride (floats) for K/V/P tiles */

// smem layout (floats): Qs[64*64] | Ks[64*65] | Vs[64*65] | Ps[64*65]
#define SMEM_FLOATS (QT * HEAD_DIM + 3 * KT * LDP)
#define SMEM_BYTES  (SMEM_FLOATS * 4)

__global__ __launch_bounds__(256) void attn_kernel(
    const float* __restrict__ Q, const float* __restrict__ K,
    const float* __restrict__ V, float* __restrict__ O)
{
    extern __shared__ float smem[];
    float* Qs = smem;                       // [64][64]
    float* Ks = Qs + QT * HEAD_DIM;         // [64][65]
    float* Vs = Ks + KT * LDP;              // [64][65]
    float* Ps = Vs + KT * LDP;              // [64][65]

    const int qt  = blockIdx.x;             // 0..31
    const int h   = blockIdx.y;
    const int b   = blockIdx.z;
    const int tid = threadIdx.x;
    const int tx  = tid & 15;
    const int ty  = tid >> 4;

    const size_t base = (size_t)b * SEQ * D_MODEL + (size_t)h * HEAD_DIM;

    // Load Q tile (64 rows x 64 cols), float4 per load
    #pragma unroll
    for (int i = 0; i < 4; i++) {
        int e  = tid + i * 256;             // 0..1023
        int r  = e >> 4;                    // 0..63
        int c4 = (e & 15) * 4;              // 0,4,...,60
        float4 qv = *(const float4*)&Q[base + (size_t)(qt * QT + r) * D_MODEL + c4];
        Qs[r * HEAD_DIM + c4 + 0] = qv.x;
        Qs[r * HEAD_DIM + c4 + 1] = qv.y;
        Qs[r * HEAD_DIM + c4 + 2] = qv.z;
        Qs[r * HEAD_DIM + c4 + 3] = qv.w;
    }

    float o_acc[4][4] = {};
    float m_r[4], l_r[4];
    #pragma unroll
    for (int i = 0; i < 4; i++) { m_r[i] = -1e30f; l_r[i] = 0.0f; }

    const float scale = 0.125f;  // 1/sqrt(64)

    for (int kt = 0; kt <= qt; kt++) {
        // Load K and V tiles
        #pragma unroll
        for (int i = 0; i < 4; i++) {
            int e  = tid + i * 256;
            int r  = e >> 4;
            int c4 = (e & 15) * 4;
            size_t g = base + (size_t)(kt * KT + r) * D_MODEL + c4;
            float4 kv = *(const float4*)&K[g];
            float4 vv = *(const float4*)&V[g];
            Ks[r * LDP + c4 + 0] = kv.x;
            Ks[r * LDP + c4 + 1] = kv.y;
            Ks[r * LDP + c4 + 2] = kv.z;
            Ks[r * LDP + c4 + 3] = kv.w;
            Vs[r * LDP + c4 + 0] = vv.x;
            Vs[r * LDP + c4 + 1] = vv.y;
            Vs[r * LDP + c4 + 2] = vv.z;
            Vs[r * LDP + c4 + 3] = vv.w;
        }
        __syncthreads();

        // S = scale * Q @ K^T  (4x4 per thread)
        float s[4][4] = {};
        #pragma unroll 8
        for (int d = 0; d < HEAD_DIM; d++) {
            float a[4], bb[4];
            #pragma unroll
            for (int i = 0; i < 4; i++) a[i]  = Qs[(ty * 4 + i) * HEAD_DIM + d];
            #pragma unroll
            for (int j = 0; j < 4; j++) bb[j] = Ks[(tx * 4 + j) * LDP + d];
            #pragma unroll
            for (int i = 0; i < 4; i++)
                #pragma unroll
                for (int j = 0; j < 4; j++)
                    s[i][j] += a[i] * bb[j];
        }
        #pragma unroll
        for (int i = 0; i < 4; i++)
            #pragma unroll
            for (int j = 0; j < 4; j++)
                s[i][j] *= scale;

        // Causal mask on the diagonal tile
        if (kt == qt) {
            #pragma unroll
            for (int i = 0; i < 4; i++)
                #pragma unroll
                for (int j = 0; j < 4; j++)
                    if (tx * 4 + j > ty * 4 + i) s[i][j] = -1e30f;
        }

        // Online softmax update (row-wise; each row owned by 16 tx lanes)
        #pragma unroll
        for (int i = 0; i < 4; i++) {
            float mt = fmaxf(fmaxf(s[i][0], s[i][1]), fmaxf(s[i][2], s[i][3]));
            #pragma unroll
            for (int off = 8; off >= 1; off >>= 1)
                mt = fmaxf(mt, __shfl_xor_sync(0xffffffffu, mt, off, 16));

            float mn    = fmaxf(m_r[i], mt);
            float alpha = __expf(m_r[i] - mn);
            m_r[i] = mn;

            float ps = 0.0f;
            #pragma unroll
            for (int j = 0; j < 4; j++) {
                s[i][j] = __expf(s[i][j] - mn);
                ps += s[i][j];
            }
            #pragma unroll
            for (int off = 8; off >= 1; off >>= 1)
                ps += __shfl_xor_sync(0xffffffffu, ps, off, 16);

            l_r[i] = l_r[i] * alpha + ps;
            #pragma unroll
            for (int j = 0; j < 4; j++) {
                o_acc[i][j] *= alpha;
                Ps[(ty * 4 + i) * LDP + tx * 4 + j] = s[i][j];
            }
        }
        __syncthreads();

        // O += P @ V
        #pragma unroll 8
        for (int ss = 0; ss < KT; ss++) {
            float pr[4], vr[4];
            #pragma unroll
            for (int i = 0; i < 4; i++) pr[i] = Ps[(ty * 4 + i) * LDP + ss];
            #pragma unroll
            for (int j = 0; j < 4; j++) vr[j] = Vs[ss * LDP + tx * 4 + j];
            #pragma unroll
            for (int i = 0; i < 4; i++)
                #pragma unroll
                for (int j = 0; j < 4; j++)
                    o_acc[i][j] += pr[i] * vr[j];
        }
        __syncthreads();
    }

    // Finalize and store
    #pragma unroll
    for (int i = 0; i < 4; i++) {
        float inv = 1.0f / l_r[i];
        int t = qt * QT + ty * 4 + i;
        #pragma unroll
        for (int j = 0; j < 4; j++)
            O[base + (size_t)t * D_MODEL + tx * 4 + j] = o_acc[i][j] * inv;
    }
}

// ---------------------------------------------------------------------------
// Launch
// ---------------------------------------------------------------------------
extern "C" void kernel_launch(void* const* d_in, const int* in_sizes, int n_in,
                              void* d_out, int out_size)
{
    const float* x  = (const float*)d_in[0];
    const float* Wq = (const float*)d_in[1];
    const float* Wk = (const float*)d_in[2];
    const float* Wv = (const float*)d_in[3];
    const float* Wo = (const float*)d_in[4];
    float* out = (float*)d_out;

    float *q, *k, *v, *o;
    cudaGetSymbolAddress((void**)&q, g_q);
    cudaGetSymbolAddress((void**)&k, g_k);
    cudaGetSymbolAddress((void**)&v, g_v);
    cudaGetSymbolAddress((void**)&o, g_o);

    dim3 gemm_grid(D_MODEL / BN, MTOT / BM);   // (16, 64)
    dim3 blk(256);

    gemm_nt_kernel<<<gemm_grid, blk>>>(x, Wq, q, MTOT, D_MODEL, D_MODEL);
    gemm_nt_kernel<<<gemm_grid, blk>>>(x, Wk, k, MTOT, D_MODEL, D_MODEL);
    gemm_nt_kernel<<<gemm_grid, blk>>>(x, Wv, v, MTOT, D_MODEL, D_MODEL);

    cudaFuncSetAttribute(attn_kernel, cudaFuncAttributeMaxDynamicSharedMemorySize,
                         SMEM_BYTES);
    dim3 attn_grid(SEQ / QT, NUM_HEADS, BATCH); // (32, 16, 2)
    attn_kernel<<<attn_grid, blk, SMEM_BYTES>>>(q, k, v, o);

    gemm_nt_kernel<<<gemm_grid, blk>>>(o, Wo, out, MTOT, D_MODEL, D_MODEL);
}

// round 6
// speedup vs baseline: 2.2338x; 2.2338x over previous
#include <cuda_runtime.h>
#include <cstdint>

#define D_MODEL   1024
#define NUM_HEADS 16
#define HEAD_DIM  64
#define BATCH     2
#define SEQ       2048
#define MTOT      (BATCH * SEQ)   /* 4096 rows */

// ---------------------------------------------------------------------------
// Scratch (device globals; no allocation allowed)
// ---------------------------------------------------------------------------
__device__ float g_q[MTOT * D_MODEL];
__device__ float g_k[MTOT * D_MODEL];
__device__ float g_v[MTOT * D_MODEL];
__device__ float g_o[MTOT * D_MODEL];

// ---------------------------------------------------------------------------
// TF32 tensor-core GEMM:  C[M,N] = A[M,K] @ B[N,K]^T  (row-major, K contig)
// Block tile 128x128, BK=32, 256 threads (8 warps as 4x2, warp tile 32x64).
// mma.sync.aligned.m16n8k8.row.col.f32.tf32.tf32.f32
// ---------------------------------------------------------------------------
#define GBM 128
#define GBN 128
#define GBK 32
#define LDS_K 36   /* padded smem stride (floats): 32 + 4 */

__device__ __forceinline__ uint32_t f2tf32(float f) {
    uint32_t r;
    asm("cvt.rna.tf32.f32 %0, %1;" : "=r"(r) : "f"(f));
    return r;
}

__device__ __forceinline__ void mma_tf32(
    float& c0, float& c1, float& c2, float& c3,
    uint32_t a0, uint32_t a1, uint32_t a2, uint32_t a3,
    uint32_t b0, uint32_t b1)
{
    asm volatile(
        "mma.sync.aligned.m16n8k8.row.col.f32.tf32.tf32.f32 "
        "{%0,%1,%2,%3}, {%4,%5,%6,%7}, {%8,%9}, {%0,%1,%2,%3};"
        : "+f"(c0), "+f"(c1), "+f"(c2), "+f"(c3)
        : "r"(a0), "r"(a1), "r"(a2), "r"(a3), "r"(b0), "r"(b1));
}

__global__ __launch_bounds__(256, 2) void gemm_tf32_kernel(
    const float* __restrict__ A, const float* __restrict__ B,
    float* __restrict__ C, int M, int N, int K)
{
    __shared__ uint32_t As[GBM * LDS_K];   // [m][k], tf32 bits
    __shared__ uint32_t Bs[GBN * LDS_K];   // [n][k], tf32 bits

    const int tid     = threadIdx.x;
    const int lane    = tid & 31;
    const int warp    = tid >> 5;
    const int groupID = lane >> 2;
    const int tig     = lane & 3;

    const int m0 = blockIdx.y * GBM;
    const int n0 = blockIdx.x * GBN;
    const int m_warp = (warp >> 1) * 32;   // 0,32,64,96
    const int n_warp = (warp & 1) * 64;    // 0,64

    float acc[2][8][4];
    #pragma unroll
    for (int mt = 0; mt < 2; mt++)
        #pragma unroll
        for (int nt = 0; nt < 8; nt++)
            #pragma unroll
            for (int c = 0; c < 4; c++) acc[mt][nt][c] = 0.0f;

    for (int k0 = 0; k0 < K; k0 += GBK) {
        // Load 128x32 tiles of A and B, converting to tf32 on the way in.
        #pragma unroll
        for (int i = 0; i < 4; i++) {
            int e  = tid + i * 256;        // 0..1023 float4-slots
            int r  = e >> 3;               // 0..127
            int c4 = (e & 7) * 4;          // 0,4,...,28
            float4 av = *(const float4*)&A[(size_t)(m0 + r) * K + k0 + c4];
            float4 bv = *(const float4*)&B[(size_t)(n0 + r) * K + k0 + c4];
            uint4 at = make_uint4(f2tf32(av.x), f2tf32(av.y), f2tf32(av.z), f2tf32(av.w));
            uint4 bt = make_uint4(f2tf32(bv.x), f2tf32(bv.y), f2tf32(bv.z), f2tf32(bv.w));
            *(uint4*)&As[r * LDS_K + c4] = at;
            *(uint4*)&Bs[r * LDS_K + c4] = bt;
        }
        __syncthreads();

        #pragma unroll
        for (int kk8 = 0; kk8 < GBK / 8; kk8++) {
            const int kb = kk8 * 8;

            uint32_t a[2][4];
            #pragma unroll
            for (int mt = 0; mt < 2; mt++) {
                int r = m_warp + mt * 16 + groupID;
                a[mt][0] = As[(r    ) * LDS_K + kb + tig    ];
                a[mt][1] = As[(r + 8) * LDS_K + kb + tig    ];
                a[mt][2] = As[(r    ) * LDS_K + kb + tig + 4];
                a[mt][3] = As[(r + 8) * LDS_K + kb + tig + 4];
            }

            uint32_t b[8][2];
            #pragma unroll
            for (int nt = 0; nt < 8; nt++) {
                int r = n_warp + nt * 8 + groupID;
                b[nt][0] = Bs[r * LDS_K + kb + tig    ];
                b[nt][1] = Bs[r * LDS_K + kb + tig + 4];
            }

            #pragma unroll
            for (int mt = 0; mt < 2; mt++)
                #pragma unroll
                for (int nt = 0; nt < 8; nt++)
                    mma_tf32(acc[mt][nt][0], acc[mt][nt][1],
                             acc[mt][nt][2], acc[mt][nt][3],
                             a[mt][0], a[mt][1], a[mt][2], a[mt][3],
                             b[nt][0], b[nt][1]);
        }
        __syncthreads();
    }

    // Epilogue: c0/c1 contiguous -> float2 stores
    #pragma unroll
    for (int mt = 0; mt < 2; mt++) {
        int row = m0 + m_warp + mt * 16 + groupID;
        #pragma unroll
        for (int nt = 0; nt < 8; nt++) {
            int col = n0 + n_warp + nt * 8 + tig * 2;
            *(float2*)&C[(size_t)(row    ) * N + col] =
                make_float2(acc[mt][nt][0], acc[mt][nt][1]);
            *(float2*)&C[(size_t)(row + 8) * N + col] =
                make_float2(acc[mt][nt][2], acc[mt][nt][3]);
        }
    }
}

// ---------------------------------------------------------------------------
// Flash-attention style causal attention, fp32, online softmax. (unchanged)
// ---------------------------------------------------------------------------
#define QT  64
#define KT  64
#define LDP 65

#define SMEM_FLOATS (QT * HEAD_DIM + 3 * KT * LDP)
#define SMEM_BYTES  (SMEM_FLOATS * 4)

__global__ __launch_bounds__(256) void attn_kernel(
    const float* __restrict__ Q, const float* __restrict__ K,
    const float* __restrict__ V, float* __restrict__ O)
{
    extern __shared__ float smem[];
    float* Qs = smem;
    float* Ks = Qs + QT * HEAD_DIM;
    float* Vs = Ks + KT * LDP;
    float* Ps = Vs + KT * LDP;

    const int qt  = blockIdx.x;
    const int h   = blockIdx.y;
    const int b   = blockIdx.z;
    const int tid = threadIdx.x;
    const int tx  = tid & 15;
    const int ty  = tid >> 4;

    const size_t base = (size_t)b * SEQ * D_MODEL + (size_t)h * HEAD_DIM;

    #pragma unroll
    for (int i = 0; i < 4; i++) {
        int e  = tid + i * 256;
        int r  = e >> 4;
        int c4 = (e & 15) * 4;
        float4 qv = *(const float4*)&Q[base + (size_t)(qt * QT + r) * D_MODEL + c4];
        Qs[r * HEAD_DIM + c4 + 0] = qv.x;
        Qs[r * HEAD_DIM + c4 + 1] = qv.y;
        Qs[r * HEAD_DIM + c4 + 2] = qv.z;
        Qs[r * HEAD_DIM + c4 + 3] = qv.w;
    }

    float o_acc[4][4] = {};
    float m_r[4], l_r[4];
    #pragma unroll
    for (int i = 0; i < 4; i++) { m_r[i] = -1e30f; l_r[i] = 0.0f; }

    const float scale = 0.125f;

    for (int kt = 0; kt <= qt; kt++) {
        #pragma unroll
        for (int i = 0; i < 4; i++) {
            int e  = tid + i * 256;
            int r  = e >> 4;
            int c4 = (e & 15) * 4;
            size_t g = base + (size_t)(kt * KT + r) * D_MODEL + c4;
            float4 kv = *(const float4*)&K[g];
            float4 vv = *(const float4*)&V[g];
            Ks[r * LDP + c4 + 0] = kv.x;
            Ks[r * LDP + c4 + 1] = kv.y;
            Ks[r * LDP + c4 + 2] = kv.z;
            Ks[r * LDP + c4 + 3] = kv.w;
            Vs[r * LDP + c4 + 0] = vv.x;
            Vs[r * LDP + c4 + 1] = vv.y;
            Vs[r * LDP + c4 + 2] = vv.z;
            Vs[r * LDP + c4 + 3] = vv.w;
        }
        __syncthreads();

        float s[4][4] = {};
        #pragma unroll 8
        for (int d = 0; d < HEAD_DIM; d++) {
            float a[4], bb[4];
            #pragma unroll
            for (int i = 0; i < 4; i++) a[i]  = Qs[(ty * 4 + i) * HEAD_DIM + d];
            #pragma unroll
            for (int j = 0; j < 4; j++) bb[j] = Ks[(tx * 4 + j) * LDP + d];
            #pragma unroll
            for (int i = 0; i < 4; i++)
                #pragma unroll
                for (int j = 0; j < 4; j++)
                    s[i][j] += a[i] * bb[j];
        }
        #pragma unroll
        for (int i = 0; i < 4; i++)
            #pragma unroll
            for (int j = 0; j < 4; j++)
                s[i][j] *= scale;

        if (kt == qt) {
            #pragma unroll
            for (int i = 0; i < 4; i++)
                #pragma unroll
                for (int j = 0; j < 4; j++)
                    if (tx * 4 + j > ty * 4 + i) s[i][j] = -1e30f;
        }

        #pragma unroll
        for (int i = 0; i < 4; i++) {
            float mt = fmaxf(fmaxf(s[i][0], s[i][1]), fmaxf(s[i][2], s[i][3]));
            #pragma unroll
            for (int off = 8; off >= 1; off >>= 1)
                mt = fmaxf(mt, __shfl_xor_sync(0xffffffffu, mt, off, 16));

            float mn    = fmaxf(m_r[i], mt);
            float alpha = __expf(m_r[i] - mn);
            m_r[i] = mn;

            float ps = 0.0f;
            #pragma unroll
            for (int j = 0; j < 4; j++) {
                s[i][j] = __expf(s[i][j] - mn);
                ps += s[i][j];
            }
            #pragma unroll
            for (int off = 8; off >= 1; off >>= 1)
                ps += __shfl_xor_sync(0xffffffffu, ps, off, 16);

            l_r[i] = l_r[i] * alpha + ps;
            #pragma unroll
            for (int j = 0; j < 4; j++) {
                o_acc[i][j] *= alpha;
                Ps[(ty * 4 + i) * LDP + tx * 4 + j] = s[i][j];
            }
        }
        __syncthreads();

        #pragma unroll 8
        for (int ss = 0; ss < KT; ss++) {
            float pr[4], vr[4];
            #pragma unroll
            for (int i = 0; i < 4; i++) pr[i] = Ps[(ty * 4 + i) * LDP + ss];
            #pragma unroll
            for (int j = 0; j < 4; j++) vr[j] = Vs[ss * LDP + tx * 4 + j];
            #pragma unroll
            for (int i = 0; i < 4; i++)
                #pragma unroll
                for (int j = 0; j < 4; j++)
                    o_acc[i][j] += pr[i] * vr[j];
        }
        __syncthreads();
    }

    #pragma unroll
    for (int i = 0; i < 4; i++) {
        float inv = 1.0f / l_r[i];
        int t = qt * QT + ty * 4 + i;
        #pragma unroll
        for (int j = 0; j < 4; j++)
            O[base + (size_t)t * D_MODEL + tx * 4 + j] = o_acc[i][j] * inv;
    }
}

// ---------------------------------------------------------------------------
// Launch
// ---------------------------------------------------------------------------
extern "C" void kernel_launch(void* const* d_in, const int* in_sizes, int n_in,
                              void* d_out, int out_size)
{
    const float* x  = (const float*)d_in[0];
    const float* Wq = (const float*)d_in[1];
    const float* Wk = (const float*)d_in[2];
    const float* Wv = (const float*)d_in[3];
    const float* Wo = (const float*)d_in[4];
    float* out = (float*)d_out;

    float *q, *k, *v, *o;
    cudaGetSymbolAddress((void**)&q, g_q);
    cudaGetSymbolAddress((void**)&k, g_k);
    cudaGetSymbolAddress((void**)&v, g_v);
    cudaGetSymbolAddress((void**)&o, g_o);

    dim3 gemm_grid(D_MODEL / GBN, MTOT / GBM);   // (8, 32)
    dim3 blk(256);

    gemm_tf32_kernel<<<gemm_grid, blk>>>(x, Wq, q, MTOT, D_MODEL, D_MODEL);
    gemm_tf32_kernel<<<gemm_grid, blk>>>(x, Wk, k, MTOT, D_MODEL, D_MODEL);
    gemm_tf32_kernel<<<gemm_grid, blk>>>(x, Wv, v, MTOT, D_MODEL, D_MODEL);

    cudaFuncSetAttribute(attn_kernel, cudaFuncAttributeMaxDynamicSharedMemorySize,
                         SMEM_BYTES);
    dim3 attn_grid(SEQ / QT, NUM_HEADS, BATCH); // (32, 16, 2)
    attn_kernel<<<attn_grid, blk, SMEM_BYTES>>>(q, k, v, o);

    gemm_tf32_kernel<<<gemm_grid, blk>>>(o, Wo, out, MTOT, D_MODEL, D_MODEL);
}

// round 10
// speedup vs baseline: 4.1788x; 1.8707x over previous
#include <cuda_runtime.h>
#include <cstdint>

#define D_MODEL   1024
#define NUM_HEADS 16
#define HEAD_DIM  64
#define BATCH     2
#define SEQ       2048
#define MTOT      (BATCH * SEQ)   /* 4096 rows */

// ---------------------------------------------------------------------------
// Scratch (device globals; no allocation allowed)
// ---------------------------------------------------------------------------
__device__ float g_q[MTOT * D_MODEL];
__device__ float g_k[MTOT * D_MODEL];
__device__ float g_v[MTOT * D_MODEL];
__device__ float g_o[MTOT * D_MODEL];

__device__ __forceinline__ uint32_t f2tf32(float f) {
    uint32_t r;
    asm("cvt.rna.tf32.f32 %0, %1;" : "=r"(r) : "f"(f));
    return r;
}

__device__ __forceinline__ void mma_tf32(
    float& c0, float& c1, float& c2, float& c3,
    uint32_t a0, uint32_t a1, uint32_t a2, uint32_t a3,
    uint32_t b0, uint32_t b1)
{
    asm volatile(
        "mma.sync.aligned.m16n8k8.row.col.f32.tf32.tf32.f32 "
        "{%0,%1,%2,%3}, {%4,%5,%6,%7}, {%8,%9}, {%0,%1,%2,%3};"
        : "+f"(c0), "+f"(c1), "+f"(c2), "+f"(c3)
        : "r"(a0), "r"(a1), "r"(a2), "r"(a3), "r"(b0), "r"(b1));
}

// ---------------------------------------------------------------------------
// TF32 tensor-core GEMM:  C[M,N] = A[M,K] @ B[N,K]^T  (row-major, K contig)
// Block tile 128x128, BK=32, 256 threads (8 warps as 4x2, warp tile 32x64).
// ---------------------------------------------------------------------------
#define GBM 128
#define GBN 128
#define GBK 32
#define LDS_K 36   /* padded smem stride (floats): 32 + 4 */

__global__ __launch_bounds__(256, 2) void gemm_tf32_kernel(
    const float* __restrict__ A, const float* __restrict__ B,
    float* __restrict__ C, int M, int N, int K)
{
    __shared__ uint32_t As[GBM * LDS_K];
    __shared__ uint32_t Bs[GBN * LDS_K];

    const int tid     = threadIdx.x;
    const int lane    = tid & 31;
    const int warp    = tid >> 5;
    const int groupID = lane >> 2;
    const int tig     = lane & 3;

    const int m0 = blockIdx.y * GBM;
    const int n0 = blockIdx.x * GBN;
    const int m_warp = (warp >> 1) * 32;
    const int n_warp = (warp & 1) * 64;

    float acc[2][8][4];
    #pragma unroll
    for (int mt = 0; mt < 2; mt++)
        #pragma unroll
        for (int nt = 0; nt < 8; nt++)
            #pragma unroll
            for (int c = 0; c < 4; c++) acc[mt][nt][c] = 0.0f;

    for (int k0 = 0; k0 < K; k0 += GBK) {
        #pragma unroll
        for (int i = 0; i < 4; i++) {
            int e  = tid + i * 256;
            int r  = e >> 3;
            int c4 = (e & 7) * 4;
            float4 av = *(const float4*)&A[(size_t)(m0 + r) * K + k0 + c4];
            float4 bv = *(const float4*)&B[(size_t)(n0 + r) * K + k0 + c4];
            uint4 at = make_uint4(f2tf32(av.x), f2tf32(av.y), f2tf32(av.z), f2tf32(av.w));
            uint4 bt = make_uint4(f2tf32(bv.x), f2tf32(bv.y), f2tf32(bv.z), f2tf32(bv.w));
            *(uint4*)&As[r * LDS_K + c4] = at;
            *(uint4*)&Bs[r * LDS_K + c4] = bt;
        }
        __syncthreads();

        #pragma unroll
        for (int kk8 = 0; kk8 < GBK / 8; kk8++) {
            const int kb = kk8 * 8;

            uint32_t a[2][4];
            #pragma unroll
            for (int mt = 0; mt < 2; mt++) {
                int r = m_warp + mt * 16 + groupID;
                a[mt][0] = As[(r    ) * LDS_K + kb + tig    ];
                a[mt][1] = As[(r + 8) * LDS_K + kb + tig    ];
                a[mt][2] = As[(r    ) * LDS_K + kb + tig + 4];
                a[mt][3] = As[(r + 8) * LDS_K + kb + tig + 4];
            }

            uint32_t b[8][2];
            #pragma unroll
            for (int nt = 0; nt < 8; nt++) {
                int r = n_warp + nt * 8 + groupID;
                b[nt][0] = Bs[r * LDS_K + kb + tig    ];
                b[nt][1] = Bs[r * LDS_K + kb + tig + 4];
            }

            #pragma unroll
            for (int mt = 0; mt < 2; mt++)
                #pragma unroll
                for (int nt = 0; nt < 8; nt++)
                    mma_tf32(acc[mt][nt][0], acc[mt][nt][1],
                             acc[mt][nt][2], acc[mt][nt][3],
                             a[mt][0], a[mt][1], a[mt][2], a[mt][3],
                             b[nt][0], b[nt][1]);
        }
        __syncthreads();
    }

    #pragma unroll
    for (int mt = 0; mt < 2; mt++) {
        int row = m0 + m_warp + mt * 16 + groupID;
        #pragma unroll
        for (int nt = 0; nt < 8; nt++) {
            int col = n0 + n_warp + nt * 8 + tig * 2;
            *(float2*)&C[(size_t)(row    ) * N + col] =
                make_float2(acc[mt][nt][0], acc[mt][nt][1]);
            *(float2*)&C[(size_t)(row + 8) * N + col] =
                make_float2(acc[mt][nt][2], acc[mt][nt][3]);
        }
    }
}

// ---------------------------------------------------------------------------
// Tensor-core flash attention (tf32 mma, fp32 softmax/accumulators).
// CTA = 128 q-rows x (head, batch). 8 warps; warp owns 16 rows.
// KV tile = 64. Q held in registers as A-frags; K as [kv][d]; V transposed
// [d][kv] in smem; P routed through smem to re-enter mma as A operand.
// ---------------------------------------------------------------------------
#define AQT  128
#define AKT  64
#define ALD  68   /* padded word stride: 64 + 4 */

#define ATTN_SMEM_WORDS (2 * AKT * ALD + AQT * ALD)
#define ATTN_SMEM_BYTES (ATTN_SMEM_WORDS * 4)

__global__ __launch_bounds__(256, 2) void attn_mma_kernel(
    const float* __restrict__ Q, const float* __restrict__ K,
    const float* __restrict__ V, float* __restrict__ O)
{
    extern __shared__ uint32_t sm[];
    uint32_t* Ks = sm;                    // [64][68]  k-rows x d
    uint32_t* Vt = Ks + AKT * ALD;        // [64][68]  d x kv (transposed)
    uint32_t* Ps = Vt + AKT * ALD;        // [128][68] q-rows x kv

    const int qtile = (int)gridDim.x - 1 - (int)blockIdx.x;  // heavy tiles first
    const int h    = blockIdx.y;
    const int b    = blockIdx.z;
    const int tid  = threadIdx.x;
    const int lane = tid & 31;
    const int warp = tid >> 5;
    const int g    = lane >> 2;
    const int tig  = lane & 3;
    const int wrow = warp * 16;

    const size_t base = (size_t)b * SEQ * D_MODEL + (size_t)h * HEAD_DIM;
    const int q0 = qtile * AQT;

    // Q fragments, pre-scaled by 1/sqrt(HEAD_DIM)
    uint32_t qf[8][4];
    {
        const float* Qr0 = Q + base + (size_t)(q0 + wrow + g) * D_MODEL;
        const float* Qr1 = Qr0 + 8 * D_MODEL;
        #pragma unroll
        for (int k8 = 0; k8 < 8; k8++) {
            qf[k8][0] = f2tf32(0.125f * Qr0[k8 * 8 + tig]);
            qf[k8][1] = f2tf32(0.125f * Qr1[k8 * 8 + tig]);
            qf[k8][2] = f2tf32(0.125f * Qr0[k8 * 8 + tig + 4]);
            qf[k8][3] = f2tf32(0.125f * Qr1[k8 * 8 + tig + 4]);
        }
    }

    float o[8][4];
    #pragma unroll
    for (int nt = 0; nt < 8; nt++)
        #pragma unroll
        for (int c = 0; c < 4; c++) o[nt][c] = 0.0f;

    float m0 = -1e30f, m1 = -1e30f, l0 = 0.0f, l1 = 0.0f;

    const int ktmax = 2 * qtile + 1;
    for (int kt = 0; kt <= ktmax; kt++) {
        // --- stage K ([kv][d]) and V transposed ([d][kv]) as tf32 bits ---
        #pragma unroll
        for (int i = 0; i < 4; i++) {
            int e  = tid + i * 256;        // 0..1023 float4-slots
            int r  = e >> 4;               // 0..63   kv row
            int c4 = (e & 15) * 4;         // 0..60   d
            size_t gaddr = base + (size_t)(kt * AKT + r) * D_MODEL + c4;
            float4 kv = *(const float4*)&K[gaddr];
            float4 vv = *(const float4*)&V[gaddr];
            uint32_t* kd = &Ks[r * ALD + c4];
            kd[0] = f2tf32(kv.x); kd[1] = f2tf32(kv.y);
            kd[2] = f2tf32(kv.z); kd[3] = f2tf32(kv.w);
            Vt[(c4 + 0) * ALD + r] = f2tf32(vv.x);
            Vt[(c4 + 1) * ALD + r] = f2tf32(vv.y);
            Vt[(c4 + 2) * ALD + r] = f2tf32(vv.z);
            Vt[(c4 + 3) * ALD + r] = f2tf32(vv.w);
        }
        __syncthreads();

        // --- S = (Q*scale) @ K^T ---
        float s[8][4];
        #pragma unroll
        for (int nt = 0; nt < 8; nt++)
            #pragma unroll
            for (int c = 0; c < 4; c++) s[nt][c] = 0.0f;

        #pragma unroll
        for (int k8 = 0; k8 < 8; k8++) {
            #pragma unroll
            for (int nt = 0; nt < 8; nt++) {
                uint32_t b0 = Ks[(nt * 8 + g) * ALD + k8 * 8 + tig    ];
                uint32_t b1 = Ks[(nt * 8 + g) * ALD + k8 * 8 + tig + 4];
                mma_tf32(s[nt][0], s[nt][1], s[nt][2], s[nt][3],
                         qf[k8][0], qf[k8][1], qf[k8][2], qf[k8][3], b0, b1);
            }
        }

        // --- causal mask (only the two diagonal-adjacent tiles) ---
        if (kt >= 2 * qtile) {
            int qr0 = q0 + wrow + g;
            int qr1 = qr0 + 8;
            #pragma unroll
            for (int nt = 0; nt < 8; nt++) {
                int c = kt * AKT + nt * 8 + tig * 2;
                if (c     > qr0) s[nt][0] = -1e30f;
                if (c + 1 > qr0) s[nt][1] = -1e30f;
                if (c     > qr1) s[nt][2] = -1e30f;
                if (c + 1 > qr1) s[nt][3] = -1e30f;
            }
        }

        // --- online softmax (rows g and g+8; quad = lanes sharing a row) ---
        float mt0 = -1e30f, mt1 = -1e30f;
        #pragma unroll
        for (int nt = 0; nt < 8; nt++) {
            mt0 = fmaxf(mt0, fmaxf(s[nt][0], s[nt][1]));
            mt1 = fmaxf(mt1, fmaxf(s[nt][2], s[nt][3]));
        }
        #pragma unroll
        for (int off = 1; off <= 2; off <<= 1) {
            mt0 = fmaxf(mt0, __shfl_xor_sync(0xffffffffu, mt0, off));
            mt1 = fmaxf(mt1, __shfl_xor_sync(0xffffffffu, mt1, off));
        }

        float mn0 = fmaxf(m0, mt0);
        float mn1 = fmaxf(m1, mt1);
        float alpha0 = __expf(m0 - mn0);
        float alpha1 = __expf(m1 - mn1);
        m0 = mn0; m1 = mn1;

        float ps0 = 0.0f, ps1 = 0.0f;
        #pragma unroll
        for (int nt = 0; nt < 8; nt++) {
            s[nt][0] = __expf(s[nt][0] - mn0);
            s[nt][1] = __expf(s[nt][1] - mn0);
            s[nt][2] = __expf(s[nt][2] - mn1);
            s[nt][3] = __expf(s[nt][3] - mn1);
            ps0 += s[nt][0] + s[nt][1];
            ps1 += s[nt][2] + s[nt][3];
        }
        #pragma unroll
        for (int off = 1; off <= 2; off <<= 1) {
            ps0 += __shfl_xor_sync(0xffffffffu, ps0, off);
            ps1 += __shfl_xor_sync(0xffffffffu, ps1, off);
        }
        l0 = l0 * alpha0 + ps0;
        l1 = l1 * alpha1 + ps1;

        #pragma unroll
        for (int nt = 0; nt < 8; nt++) {
            o[nt][0] *= alpha0; o[nt][1] *= alpha0;
            o[nt][2] *= alpha1; o[nt][3] *= alpha1;
        }

        // --- write P to smem (tf32 bits), re-enter as A operand ---
        {
            uint32_t* pr0 = &Ps[(wrow + g    ) * ALD];
            uint32_t* pr1 = &Ps[(wrow + g + 8) * ALD];
            #pragma unroll
            for (int nt = 0; nt < 8; nt++) {
                int c = nt * 8 + tig * 2;
                pr0[c    ] = f2tf32(s[nt][0]);
                pr0[c + 1] = f2tf32(s[nt][1]);
                pr1[c    ] = f2tf32(s[nt][2]);
                pr1[c + 1] = f2tf32(s[nt][3]);
            }
        }
        __syncwarp();   // own-warp cross-lane STS->LDS visibility

        // --- O += P @ V ---
        #pragma unroll
        for (int k8 = 0; k8 < 8; k8++) {
            uint32_t af0 = Ps[(wrow + g    ) * ALD + k8 * 8 + tig    ];
            uint32_t af1 = Ps[(wrow + g + 8) * ALD + k8 * 8 + tig    ];
            uint32_t af2 = Ps[(wrow + g    ) * ALD + k8 * 8 + tig + 4];
            uint32_t af3 = Ps[(wrow + g + 8) * ALD + k8 * 8 + tig + 4];
            #pragma unroll
            for (int nt = 0; nt < 8; nt++) {
                uint32_t b0 = Vt[(nt * 8 + g) * ALD + k8 * 8 + tig    ];
                uint32_t b1 = Vt[(nt * 8 + g) * ALD + k8 * 8 + tig + 4];
                mma_tf32(o[nt][0], o[nt][1], o[nt][2], o[nt][3],
                         af0, af1, af2, af3, b0, b1);
            }
        }
        __syncthreads();   // protect Ks/Vt before next tile's staging
    }

    // --- finalize ---
    float inv0 = 1.0f / l0;
    float inv1 = 1.0f / l1;
    float* Or0 = O + base + (size_t)(q0 + wrow + g) * D_MODEL;
    float* Or1 = Or0 + 8 * D_MODEL;
    #pragma unroll
    for (int nt = 0; nt < 8; nt++) {
        int c = nt * 8 + tig * 2;
        *(float2*)&Or0[c] = make_float2(o[nt][0] * inv0, o[nt][1] * inv0);
        *(float2*)&Or1[c] = make_float2(o[nt][2] * inv1, o[nt][3] * inv1);
    }
}

// ---------------------------------------------------------------------------
// Launch
// ---------------------------------------------------------------------------
extern "C" void kernel_launch(void* const* d_in, const int* in_sizes, int n_in,
                              void* d_out, int out_size)
{
    const float* x  = (const float*)d_in[0];
    const float* Wq = (const float*)d_in[1];
    const float* Wk = (const float*)d_in[2];
    const float* Wv = (const float*)d_in[3];
    const float* Wo = (const float*)d_in[4];
    float* out = (float*)d_out;

    float *q, *k, *v, *o;
    cudaGetSymbolAddress((void**)&q, g_q);
    cudaGetSymbolAddress((void**)&k, g_k);
    cudaGetSymbolAddress((void**)&v, g_v);
    cudaGetSymbolAddress((void**)&o, g_o);

    dim3 gemm_grid(D_MODEL / GBN, MTOT / GBM);   // (8, 32)
    dim3 blk(256);

    gemm_tf32_kernel<<<gemm_grid, blk>>>(x, Wq, q, MTOT, D_MODEL, D_MODEL);
    gemm_tf32_kernel<<<gemm_grid, blk>>>(x, Wk, k, MTOT, D_MODEL, D_MODEL);
    gemm_tf32_kernel<<<gemm_grid, blk>>>(x, Wv, v, MTOT, D_MODEL, D_MODEL);

    cudaFuncSetAttribute(attn_mma_kernel,
                         cudaFuncAttributeMaxDynamicSharedMemorySize,
                         ATTN_SMEM_BYTES);
    dim3 attn_grid(SEQ / AQT, NUM_HEADS, BATCH);  // (16, 16, 2)
    attn_mma_kernel<<<attn_grid, blk, ATTN_SMEM_BYTES>>>(q, k, v, o);

    gemm_tf32_kernel<<<gemm_grid, blk>>>(o, Wo, out, MTOT, D_MODEL, D_MODEL);
}